// round 2
// baseline (speedup 1.0000x reference)
#include <cuda_runtime.h>
#include <cuda_bf16.h>
#include <cstdint>

// Problem constants (shapes fixed by the reference)
#define IN_F   256
#define OUT_F  64
#define MAX_NODES 100000

// Scratch: support = x @ W  (100000 x 64 fp32 = 25.6 MB). Static __device__
// array (no allocation APIs allowed).
__device__ float g_support[(size_t)MAX_NODES * OUT_F];

// ---------------------------------------------------------------------------
// Kernel 1: GEMM  support[n][64] = x[n][256] @ W[256][64]
// Block: 256 threads, TILE_M = 128 rows, K staged in 32-wide chunks.
// Per thread: 4 rows x 8 cols register tile (32 accumulators).
//   thread layout: cg = tid & 7 (col group, 8 cols each), rg = tid >> 3
// smem: xs[128][33] (pad -> conflict-free), ws[32][64] (broadcast reads)
// ---------------------------------------------------------------------------
#define TILE_M 128
#define KCHUNK 32

__global__ __launch_bounds__(256, 4)
void gemm_kernel(const float* __restrict__ x,
                 const float* __restrict__ w,
                 float* __restrict__ support,
                 int n_nodes)
{
    __shared__ float xs[TILE_M][KCHUNK + 1];   // stride 33 floats
    __shared__ float ws[KCHUNK][OUT_F];        // stride 64 floats

    const int tid = threadIdx.x;
    const int cg  = tid & 7;    // 0..7  -> cols [cg*8, cg*8+8)
    const int rg  = tid >> 3;   // 0..31 -> rows [rg*4, rg*4+4) within tile
    const int row_base = blockIdx.x * TILE_M;

    float acc[4][8];
#pragma unroll
    for (int i = 0; i < 4; i++)
#pragma unroll
        for (int j = 0; j < 8; j++) acc[i][j] = 0.0f;

    for (int k0 = 0; k0 < IN_F; k0 += KCHUNK) {
        __syncthreads();  // protect previous chunk's smem

        // ---- load x tile: 128 rows x 32 cols. 8 float4/row -> 8 threads/row,
        //      32 rows per pass, 4 passes.
        {
            const int c4 = tid & 7;          // float4 index within the chunk
            const int r0 = tid >> 3;         // 0..31
#pragma unroll
            for (int p = 0; p < 4; p++) {
                int r = r0 + p * 32;
                int grow = row_base + r;
                int gr = (grow < n_nodes) ? grow : (n_nodes - 1);  // clamp
                float4 v = *reinterpret_cast<const float4*>(
                    x + (size_t)gr * IN_F + k0 + c4 * 4);
                xs[r][c4 * 4 + 0] = v.x;
                xs[r][c4 * 4 + 1] = v.y;
                xs[r][c4 * 4 + 2] = v.z;
                xs[r][c4 * 4 + 3] = v.w;
            }
        }
        // ---- load W chunk: 32x64 floats = 512 float4, 2 per thread
        {
            const float4* wsrc = reinterpret_cast<const float4*>(w + (size_t)k0 * OUT_F);
            float4* wdst = reinterpret_cast<float4*>(&ws[0][0]);
            wdst[tid]       = wsrc[tid];
            wdst[tid + 256] = wsrc[tid + 256];
        }
        __syncthreads();

        // ---- compute
#pragma unroll 8
        for (int k = 0; k < KCHUNK; k++) {
            float4 w0 = *reinterpret_cast<const float4*>(&ws[k][cg * 8]);
            float4 w1 = *reinterpret_cast<const float4*>(&ws[k][cg * 8 + 4]);
            float wv[8] = {w0.x, w0.y, w0.z, w0.w, w1.x, w1.y, w1.z, w1.w};
#pragma unroll
            for (int rr = 0; rr < 4; rr++) {
                float xv = xs[rg * 4 + rr][k];
#pragma unroll
                for (int j = 0; j < 8; j++)
                    acc[rr][j] = fmaf(xv, wv[j], acc[rr][j]);
            }
        }
    }

    // ---- epilogue: 4 rows x 8 cols (2 float4 per row)
#pragma unroll
    for (int rr = 0; rr < 4; rr++) {
        int row = row_base + rg * 4 + rr;
        if (row < n_nodes) {
            float* dst = support + (size_t)row * OUT_F + cg * 8;
            float4 o0 = make_float4(acc[rr][0], acc[rr][1], acc[rr][2], acc[rr][3]);
            float4 o1 = make_float4(acc[rr][4], acc[rr][5], acc[rr][6], acc[rr][7]);
            *reinterpret_cast<float4*>(dst)     = o0;
            *reinterpret_cast<float4*>(dst + 4) = o1;
        }
    }
}

// ---------------------------------------------------------------------------
// Kernel 2: out[n][f] = b[f]   (bias broadcast; atomics accumulate on top)
// ---------------------------------------------------------------------------
__global__ __launch_bounds__(256)
void init_out_kernel(float* __restrict__ out, const float* __restrict__ b,
                     int total4)   // number of float4 elements
{
    int i4 = blockIdx.x * blockDim.x + threadIdx.x;
    if (i4 < total4) {
        // column of this float4 within the 64-wide row: (i4 & 15) * 4
        float4 bv = *reinterpret_cast<const float4*>(b + ((i4 & 15) * 4));
        reinterpret_cast<float4*>(out)[i4] = bv;
    }
}

// ---------------------------------------------------------------------------
// Kernel 3: edge scatter. 16 threads per edge; each handles 4 consecutive
// outputs via float4 gather + vectorized red.global.add.v4.f32.
// ---------------------------------------------------------------------------
__global__ __launch_bounds__(256)
void spmm_kernel(const int* __restrict__ adj_row,
                 const int* __restrict__ adj_col,
                 const float* __restrict__ adj_vals,
                 const float* __restrict__ support,
                 float* __restrict__ out,
                 int n_edges)
{
    int t = blockIdx.x * blockDim.x + threadIdx.x;
    int e = t >> 4;
    if (e >= n_edges) return;
    int lane = t & 15;

    int   r = __ldg(adj_row + e);
    int   c = __ldg(adj_col + e);
    float v = __ldg(adj_vals + e);

    float4 s = *reinterpret_cast<const float4*>(support + (size_t)c * OUT_F + lane * 4);
    float gx = s.x * v, gy = s.y * v, gz = s.z * v, gw = s.w * v;

    float* dst = out + (size_t)r * OUT_F + lane * 4;
    // PTX ISA vectorized reduction (sm_90+): op precedes vector type.
    asm volatile("red.global.add.v4.f32 [%0], {%1, %2, %3, %4};"
                 :: "l"(dst), "f"(gx), "f"(gy), "f"(gz), "f"(gw)
                 : "memory");
}

// ---------------------------------------------------------------------------
// Launch
// Inputs (metadata order): x, adj_row, adj_col, adj_vals, weight, b
// ---------------------------------------------------------------------------
extern "C" void kernel_launch(void* const* d_in, const int* in_sizes, int n_in,
                              void* d_out, int out_size)
{
    const float* x        = (const float*)d_in[0];
    const int*   adj_row  = (const int*)  d_in[1];
    const int*   adj_col  = (const int*)  d_in[2];
    const float* adj_vals = (const float*)d_in[3];
    const float* weight   = (const float*)d_in[4];
    const float* b        = (const float*)d_in[5];
    float* out = (float*)d_out;

    const int n_nodes = in_sizes[0] / IN_F;
    const int n_edges = in_sizes[1];

    float* support = nullptr;
    cudaGetSymbolAddress((void**)&support, g_support);

    // 1) GEMM
    int gemm_blocks = (n_nodes + TILE_M - 1) / TILE_M;
    gemm_kernel<<<gemm_blocks, 256>>>(x, weight, support, n_nodes);

    // 2) out = bias broadcast
    int total4 = n_nodes * OUT_F / 4;
    init_out_kernel<<<(total4 + 255) / 256, 256>>>(out, b, total4);

    // 3) edge scatter (16 threads / edge)
    long long threads = (long long)n_edges * 16;
    int blocks = (int)((threads + 255) / 256);
    spmm_kernel<<<blocks, 256>>>(adj_row, adj_col, adj_vals, support, out, n_edges);
}

// round 5
// speedup vs baseline: 1.6404x; 1.6404x over previous
#include <cuda_runtime.h>
#include <cuda_bf16.h>
#include <cstdint>

#define IN_F   256
#define OUT_F  64
#define MAX_NODES 100000

// ---------------------------------------------------------------------------
// Device scratch (no allocation APIs allowed)
// ---------------------------------------------------------------------------
__device__ float g_support[(size_t)MAX_NODES * OUT_F];
// Pre-packed per-lane B fragments of W (bf16 hi/lo split) for
// mma.sync.m16n8k16.row.col: layout [img(2)][ks(16)][nt(8)][lane(32)] u64.
// Each u64 = {b0,b1} lo32, {b2,b3} hi32.  Total 8192 * 8B = 64 KB.
__device__ unsigned long long g_bfrag[2 * 16 * 8 * 32];

// ---------------------------------------------------------------------------
// helpers
// ---------------------------------------------------------------------------
__device__ __forceinline__ uint32_t bfpack(float a, float b) {
    __nv_bfloat162 t = __floats2bfloat162_rn(a, b);
    return *reinterpret_cast<uint32_t*>(&t);
}
__device__ __forceinline__ void bfsplit(float v, float& hi, float& lo) {
    __nv_bfloat16 h = __float2bfloat16(v);
    hi = __bfloat162float(h);
    lo = v - hi;
}
__device__ __forceinline__ void mma_bf16(float* c, const uint32_t* a,
                                         uint32_t b0, uint32_t b1) {
    asm volatile(
        "mma.sync.aligned.m16n8k16.row.col.f32.bf16.bf16.f32 "
        "{%0,%1,%2,%3}, {%4,%5,%6,%7}, {%8,%9}, {%0,%1,%2,%3};"
        : "+f"(c[0]), "+f"(c[1]), "+f"(c[2]), "+f"(c[3])
        : "r"(a[0]), "r"(a[1]), "r"(a[2]), "r"(a[3]), "r"(b0), "r"(b1));
}

// ---------------------------------------------------------------------------
// Kernel 0: pack W into per-lane B fragments (hi and lo bf16 images).
// B frag (k16 x n8, col-major) per lane: col = nt*8 + (lane>>2),
// rows = ks*16 + (lane&3)*2 + {0,1} (b0,b1) and +8 (b2,b3).
// w global layout: [K=256][N=64] row-major.
// ---------------------------------------------------------------------------
__global__ __launch_bounds__(256)
void prep_w_kernel(const float* __restrict__ w) {
    int idx = blockIdx.x * 256 + threadIdx.x;   // 0 .. 4095
    if (idx >= 16 * 8 * 32) return;
    int lane = idx & 31;
    int nt   = (idx >> 5) & 7;
    int ks   = idx >> 8;

    int col = nt * 8 + (lane >> 2);
    int r   = ks * 16 + (lane & 3) * 2;

    float v0 = w[(size_t)(r    ) * OUT_F + col];
    float v1 = w[(size_t)(r + 1) * OUT_F + col];
    float v2 = w[(size_t)(r + 8) * OUT_F + col];
    float v3 = w[(size_t)(r + 9) * OUT_F + col];

    float h0,l0,h1,l1,h2,l2,h3,l3;
    bfsplit(v0,h0,l0); bfsplit(v1,h1,l1); bfsplit(v2,h2,l2); bfsplit(v3,h3,l3);

    unsigned long long hi = (unsigned long long)bfpack(h0,h1)
                          | ((unsigned long long)bfpack(h2,h3) << 32);
    unsigned long long lo = (unsigned long long)bfpack(l0,l1)
                          | ((unsigned long long)bfpack(l2,l3) << 32);

    g_bfrag[idx]              = hi;   // img 0
    g_bfrag[16*8*32 + idx]    = lo;   // img 1
}

// ---------------------------------------------------------------------------
// Kernel 1: GEMM via mma.sync bf16, 3-pass split precision.
// 256 threads / block, 128 rows / block, warp owns 16 rows x 64 cols.
// Passes: Ahi*Bhi + Alo*Bhi + Ahi*Blo  (Alo*Blo ~2^-18, dropped).
// ---------------------------------------------------------------------------
__global__ __launch_bounds__(256)
void gemm_mma_kernel(const float* __restrict__ x,
                     float* __restrict__ support,
                     int n_nodes)
{
    extern __shared__ unsigned long long sm_bfrag[];   // [2][16][8][32] = 64 KB

    const int tid  = threadIdx.x;
    const int wid  = tid >> 5;
    const int lane = tid & 31;

    // copy B fragments to smem (4096 float4)
    {
        const float4* src = reinterpret_cast<const float4*>(g_bfrag);
        float4* dst = reinterpret_cast<float4*>(sm_bfrag);
#pragma unroll
        for (int i = 0; i < 16; i++)
            dst[tid + i * 256] = src[tid + i * 256];
    }
    __syncthreads();

    const int row_base = blockIdx.x * 128 + wid * 16;
    int r0 = row_base + (lane >> 2);
    int r1 = r0 + 8;
    int r0c = (r0 < n_nodes) ? r0 : (n_nodes - 1);
    int r1c = (r1 < n_nodes) ? r1 : (n_nodes - 1);
    const float* xr0 = x + (size_t)r0c * IN_F;
    const float* xr1 = x + (size_t)r1c * IN_F;
    const int cbase = (lane & 3) * 2;

    float acc[8][4];
#pragma unroll
    for (int nt = 0; nt < 8; nt++)
#pragma unroll
        for (int j = 0; j < 4; j++) acc[nt][j] = 0.0f;

#pragma unroll 4
    for (int ks = 0; ks < 16; ks++) {
        int c0 = ks * 16 + cbase;
        // ---- A fragments (hi/lo) straight from global
        float2 p00 = *reinterpret_cast<const float2*>(xr0 + c0);
        float2 p10 = *reinterpret_cast<const float2*>(xr1 + c0);
        float2 p01 = *reinterpret_cast<const float2*>(xr0 + c0 + 8);
        float2 p11 = *reinterpret_cast<const float2*>(xr1 + c0 + 8);

        float h,l, h2,l2;
        uint32_t ahi[4], alo[4];
        bfsplit(p00.x, h, l); bfsplit(p00.y, h2, l2);
        ahi[0] = bfpack(h, h2);  alo[0] = bfpack(l, l2);
        bfsplit(p10.x, h, l); bfsplit(p10.y, h2, l2);
        ahi[1] = bfpack(h, h2);  alo[1] = bfpack(l, l2);
        bfsplit(p01.x, h, l); bfsplit(p01.y, h2, l2);
        ahi[2] = bfpack(h, h2);  alo[2] = bfpack(l, l2);
        bfsplit(p11.x, h, l); bfsplit(p11.y, h2, l2);
        ahi[3] = bfpack(h, h2);  alo[3] = bfpack(l, l2);

        // ---- B hi fragments: passes 1 & 2
        const unsigned long long* bh = sm_bfrag + (size_t)ks * (8 * 32) + lane;
        unsigned long long bf[8];
#pragma unroll
        for (int nt = 0; nt < 8; nt++) bf[nt] = bh[nt * 32];
#pragma unroll
        for (int nt = 0; nt < 8; nt++) {
            uint32_t b0 = (uint32_t)bf[nt], b1 = (uint32_t)(bf[nt] >> 32);
            mma_bf16(acc[nt], ahi, b0, b1);
            mma_bf16(acc[nt], alo, b0, b1);
        }
        // ---- B lo fragments: pass 3
        const unsigned long long* bl = bh + 16 * 8 * 32;
#pragma unroll
        for (int nt = 0; nt < 8; nt++) bf[nt] = bl[nt * 32];
#pragma unroll
        for (int nt = 0; nt < 8; nt++) {
            uint32_t b0 = (uint32_t)bf[nt], b1 = (uint32_t)(bf[nt] >> 32);
            mma_bf16(acc[nt], ahi, b0, b1);
        }
    }

    // ---- store D: c0,c1 -> row r0 cols nt*8+cbase; c2,c3 -> row r1
    if (r0 < n_nodes) {
        float* d = support + (size_t)r0 * OUT_F + cbase;
#pragma unroll
        for (int nt = 0; nt < 8; nt++)
            *reinterpret_cast<float2*>(d + nt * 8) = make_float2(acc[nt][0], acc[nt][1]);
    }
    if (r1 < n_nodes) {
        float* d = support + (size_t)r1 * OUT_F + cbase;
#pragma unroll
        for (int nt = 0; nt < 8; nt++)
            *reinterpret_cast<float2*>(d + nt * 8) = make_float2(acc[nt][2], acc[nt][3]);
    }
}

// ---------------------------------------------------------------------------
// Kernel 2: out[n][f] = b[f]  (bias broadcast; atomics accumulate on top)
// ---------------------------------------------------------------------------
__global__ __launch_bounds__(256)
void init_out_kernel(float* __restrict__ out, const float* __restrict__ b,
                     int total4)
{
    int i4 = blockIdx.x * blockDim.x + threadIdx.x;
    if (i4 < total4) {
        float4 bv = *reinterpret_cast<const float4*>(b + ((i4 & 15) * 4));
        reinterpret_cast<float4*>(out)[i4] = bv;
    }
}

// ---------------------------------------------------------------------------
// Kernel 3: edge scatter. 16 threads/edge, float4 gather + red.global.add.v4.
// ---------------------------------------------------------------------------
__global__ __launch_bounds__(256)
void spmm_kernel(const int* __restrict__ adj_row,
                 const int* __restrict__ adj_col,
                 const float* __restrict__ adj_vals,
                 const float* __restrict__ support,
                 float* __restrict__ out,
                 int n_edges)
{
    int t = blockIdx.x * blockDim.x + threadIdx.x;
    int e = t >> 4;
    if (e >= n_edges) return;
    int lane = t & 15;

    int   r = __ldg(adj_row + e);
    int   c = __ldg(adj_col + e);
    float v = __ldg(adj_vals + e);

    float4 s = *reinterpret_cast<const float4*>(support + (size_t)c * OUT_F + lane * 4);
    float gx = s.x * v, gy = s.y * v, gz = s.z * v, gw = s.w * v;

    float* dst = out + (size_t)r * OUT_F + lane * 4;
    asm volatile("red.global.add.v4.f32 [%0], {%1, %2, %3, %4};"
                 :: "l"(dst), "f"(gx), "f"(gy), "f"(gz), "f"(gw)
                 : "memory");
}

// ---------------------------------------------------------------------------
// Launch.  Inputs (metadata order): x, adj_row, adj_col, adj_vals, weight, b
// ---------------------------------------------------------------------------
extern "C" void kernel_launch(void* const* d_in, const int* in_sizes, int n_in,
                              void* d_out, int out_size)
{
    const float* x        = (const float*)d_in[0];
    const int*   adj_row  = (const int*)  d_in[1];
    const int*   adj_col  = (const int*)  d_in[2];
    const float* adj_vals = (const float*)d_in[3];
    const float* weight   = (const float*)d_in[4];
    const float* b        = (const float*)d_in[5];
    float* out = (float*)d_out;

    const int n_nodes = in_sizes[0] / IN_F;
    const int n_edges = in_sizes[1];

    float* support = nullptr;
    cudaGetSymbolAddress((void**)&support, g_support);

    // 64 KB dynamic smem for the GEMM (idempotent; capture-safe host call)
    cudaFuncSetAttribute(gemm_mma_kernel,
                         cudaFuncAttributeMaxDynamicSharedMemorySize, 65536);

    // 0) pack W into bf16 hi/lo MMA fragments
    prep_w_kernel<<<16, 256>>>(weight);

    // 1) tensor-core GEMM (legacy HMMA mma.sync path)
    int gemm_blocks = (n_nodes + 127) / 128;
    gemm_mma_kernel<<<gemm_blocks, 256, 65536>>>(x, support, n_nodes);

    // 2) out = bias broadcast
    int total4 = n_nodes * OUT_F / 4;
    init_out_kernel<<<(total4 + 255) / 256, 256>>>(out, b, total4);

    // 3) edge scatter
    long long threads = (long long)n_edges * 16;
    int blocks = (int)((threads + 255) / 256);
    spmm_kernel<<<blocks, 256>>>(adj_row, adj_col, adj_vals, support, out, n_edges);
}

// round 7
// speedup vs baseline: 1.7424x; 1.0621x over previous
#include <cuda_runtime.h>
#include <cuda_bf16.h>
#include <cstdint>

#define IN_F   256
#define OUT_F  64
#define MAX_NODES 100000
#define MAX_EDGES 1600000

// ---------------------------------------------------------------------------
// Device scratch (no allocation APIs allowed)
// ---------------------------------------------------------------------------
__device__ float g_support[(size_t)MAX_NODES * OUT_F];
__device__ unsigned long long g_bfrag[2 * 16 * 8 * 32];   // W mma fragments

// CSR build scratch
__device__ int   g_deg[MAX_NODES];        // per-row edge count (histogram)
__device__ int   g_rs[MAX_NODES];         // in-block exclusive scan
__device__ int   g_part[64];              // per-scan-block totals
__device__ int   g_row_start[MAX_NODES];  // final exclusive scan
__device__ int   g_cursor[MAX_NODES];     // scatter cursors
__device__ int   g_ecol[MAX_EDGES];       // CSR cols
__device__ float g_eval[MAX_EDGES];       // CSR vals

#define SCAN_T 512
#define SCAN_E 8
#define SCAN_CHUNK (SCAN_T * SCAN_E)      // 4096

// ---------------------------------------------------------------------------
// helpers
// ---------------------------------------------------------------------------
__device__ __forceinline__ uint32_t bfpack(float a, float b) {
    __nv_bfloat162 t = __floats2bfloat162_rn(a, b);
    return *reinterpret_cast<uint32_t*>(&t);
}
__device__ __forceinline__ void bfsplit(float v, float& hi, float& lo) {
    __nv_bfloat16 h = __float2bfloat16(v);
    hi = __bfloat162float(h);
    lo = v - hi;
}
__device__ __forceinline__ void mma_bf16(float* c, const uint32_t* a,
                                         uint32_t b0, uint32_t b1) {
    asm volatile(
        "mma.sync.aligned.m16n8k16.row.col.f32.bf16.bf16.f32 "
        "{%0,%1,%2,%3}, {%4,%5,%6,%7}, {%8,%9}, {%0,%1,%2,%3};"
        : "+f"(c[0]), "+f"(c[1]), "+f"(c[2]), "+f"(c[3])
        : "r"(a[0]), "r"(a[1]), "r"(a[2]), "r"(a[3]), "r"(b0), "r"(b1));
}

// ---------------------------------------------------------------------------
// Kernel 0: pack W into per-lane B fragments (hi and lo bf16 images).
// ---------------------------------------------------------------------------
__global__ __launch_bounds__(256)
void prep_w_kernel(const float* __restrict__ w) {
    int idx = blockIdx.x * 256 + threadIdx.x;   // 0 .. 4095
    if (idx >= 16 * 8 * 32) return;
    int lane = idx & 31;
    int nt   = (idx >> 5) & 7;
    int ks   = idx >> 8;

    int col = nt * 8 + (lane >> 2);
    int r   = ks * 16 + (lane & 3) * 2;

    float v0 = w[(size_t)(r    ) * OUT_F + col];
    float v1 = w[(size_t)(r + 1) * OUT_F + col];
    float v2 = w[(size_t)(r + 8) * OUT_F + col];
    float v3 = w[(size_t)(r + 9) * OUT_F + col];

    float h0,l0,h1,l1,h2,l2,h3,l3;
    bfsplit(v0,h0,l0); bfsplit(v1,h1,l1); bfsplit(v2,h2,l2); bfsplit(v3,h3,l3);

    unsigned long long hi = (unsigned long long)bfpack(h0,h1)
                          | ((unsigned long long)bfpack(h2,h3) << 32);
    unsigned long long lo = (unsigned long long)bfpack(l0,l1)
                          | ((unsigned long long)bfpack(l2,l3) << 32);

    g_bfrag[idx]           = hi;
    g_bfrag[16*8*32 + idx] = lo;
}

// ---------------------------------------------------------------------------
// Kernel 1: GEMM via mma.sync bf16, 3-pass split precision (proven R5)
// ---------------------------------------------------------------------------
__global__ __launch_bounds__(256)
void gemm_mma_kernel(const float* __restrict__ x,
                     float* __restrict__ support,
                     int n_nodes)
{
    extern __shared__ unsigned long long sm_bfrag[];   // 64 KB

    const int tid  = threadIdx.x;
    const int wid  = tid >> 5;
    const int lane = tid & 31;

    {
        const float4* src = reinterpret_cast<const float4*>(g_bfrag);
        float4* dst = reinterpret_cast<float4*>(sm_bfrag);
#pragma unroll
        for (int i = 0; i < 16; i++)
            dst[tid + i * 256] = src[tid + i * 256];
    }
    __syncthreads();

    const int row_base = blockIdx.x * 128 + wid * 16;
    int r0 = row_base + (lane >> 2);
    int r1 = r0 + 8;
    int r0c = (r0 < n_nodes) ? r0 : (n_nodes - 1);
    int r1c = (r1 < n_nodes) ? r1 : (n_nodes - 1);
    const float* xr0 = x + (size_t)r0c * IN_F;
    const float* xr1 = x + (size_t)r1c * IN_F;
    const int cbase = (lane & 3) * 2;

    float acc[8][4];
#pragma unroll
    for (int nt = 0; nt < 8; nt++)
#pragma unroll
        for (int j = 0; j < 4; j++) acc[nt][j] = 0.0f;

#pragma unroll 4
    for (int ks = 0; ks < 16; ks++) {
        int c0 = ks * 16 + cbase;
        float2 p00 = *reinterpret_cast<const float2*>(xr0 + c0);
        float2 p10 = *reinterpret_cast<const float2*>(xr1 + c0);
        float2 p01 = *reinterpret_cast<const float2*>(xr0 + c0 + 8);
        float2 p11 = *reinterpret_cast<const float2*>(xr1 + c0 + 8);

        float h,l, h2,l2;
        uint32_t ahi[4], alo[4];
        bfsplit(p00.x, h, l); bfsplit(p00.y, h2, l2);
        ahi[0] = bfpack(h, h2);  alo[0] = bfpack(l, l2);
        bfsplit(p10.x, h, l); bfsplit(p10.y, h2, l2);
        ahi[1] = bfpack(h, h2);  alo[1] = bfpack(l, l2);
        bfsplit(p01.x, h, l); bfsplit(p01.y, h2, l2);
        ahi[2] = bfpack(h, h2);  alo[2] = bfpack(l, l2);
        bfsplit(p11.x, h, l); bfsplit(p11.y, h2, l2);
        ahi[3] = bfpack(h, h2);  alo[3] = bfpack(l, l2);

        const unsigned long long* bh = sm_bfrag + (size_t)ks * (8 * 32) + lane;
        unsigned long long bf[8];
#pragma unroll
        for (int nt = 0; nt < 8; nt++) bf[nt] = bh[nt * 32];
#pragma unroll
        for (int nt = 0; nt < 8; nt++) {
            uint32_t b0 = (uint32_t)bf[nt], b1 = (uint32_t)(bf[nt] >> 32);
            mma_bf16(acc[nt], ahi, b0, b1);
            mma_bf16(acc[nt], alo, b0, b1);
        }
        const unsigned long long* bl = bh + 16 * 8 * 32;
#pragma unroll
        for (int nt = 0; nt < 8; nt++) bf[nt] = bl[nt * 32];
#pragma unroll
        for (int nt = 0; nt < 8; nt++) {
            uint32_t b0 = (uint32_t)bf[nt], b1 = (uint32_t)(bf[nt] >> 32);
            mma_bf16(acc[nt], ahi, b0, b1);
        }
    }

    if (r0 < n_nodes) {
        float* d = support + (size_t)r0 * OUT_F + cbase;
#pragma unroll
        for (int nt = 0; nt < 8; nt++)
            *reinterpret_cast<float2*>(d + nt * 8) = make_float2(acc[nt][0], acc[nt][1]);
    }
    if (r1 < n_nodes) {
        float* d = support + (size_t)r1 * OUT_F + cbase;
#pragma unroll
        for (int nt = 0; nt < 8; nt++)
            *reinterpret_cast<float2*>(d + nt * 8) = make_float2(acc[nt][2], acc[nt][3]);
    }
}

// ---------------------------------------------------------------------------
// CSR build
// ---------------------------------------------------------------------------
__global__ __launch_bounds__(256)
void hist_kernel(const int* __restrict__ adj_row, int n_edges) {
    int e = blockIdx.x * 256 + threadIdx.x;
    if (e < n_edges) atomicAdd(&g_deg[adj_row[e]], 1);
}

// scan1: per-block exclusive scan of deg into g_rs, block totals into g_part
__global__ __launch_bounds__(SCAN_T)
void scan1_kernel(int n) {
    __shared__ int s[SCAN_T];
    const int tid = threadIdx.x;
    const int base = blockIdx.x * SCAN_CHUNK + tid * SCAN_E;

    int c[SCAN_E];
    int tsum = 0;
#pragma unroll
    for (int j = 0; j < SCAN_E; j++) {
        int idx = base + j;
        c[j] = (idx < n) ? g_deg[idx] : 0;
        tsum += c[j];
    }
    s[tid] = tsum;
    __syncthreads();
    // Hillis-Steele inclusive scan over 512 thread sums
    for (int off = 1; off < SCAN_T; off <<= 1) {
        int v = (tid >= off) ? s[tid - off] : 0;
        __syncthreads();
        s[tid] += v;
        __syncthreads();
    }
    int excl = s[tid] - tsum;
    if (tid == SCAN_T - 1) g_part[blockIdx.x] = s[tid];  // block total
#pragma unroll
    for (int j = 0; j < SCAN_E; j++) {
        int idx = base + j;
        if (idx < n) g_rs[idx] = excl;
        excl += c[j];
    }
}

// scan2: exclusive scan of block totals (tiny)
__global__ void scan2_kernel(int nblocks) {
    if (threadIdx.x == 0) {
        int run = 0;
        for (int i = 0; i < nblocks; i++) {
            int v = g_part[i];
            g_part[i] = run;
            run += v;
        }
    }
}

// scan3: add block offsets; init row_start + cursor
__global__ __launch_bounds__(256)
void scan3_kernel(int n) {
    int idx = blockIdx.x * 256 + threadIdx.x;
    if (idx < n) {
        int v = g_rs[idx] + g_part[idx / SCAN_CHUNK];
        g_row_start[idx] = v;
        g_cursor[idx] = v;
    }
}

__global__ __launch_bounds__(256)
void scatter_kernel(const int* __restrict__ adj_row,
                    const int* __restrict__ adj_col,
                    const float* __restrict__ adj_vals,
                    int n_edges) {
    int e = blockIdx.x * 256 + threadIdx.x;
    if (e < n_edges) {
        int r = adj_row[e];
        int pos = atomicAdd(&g_cursor[r], 1);
        g_ecol[pos] = adj_col[e];
        g_eval[pos] = adj_vals[e];
    }
}

// ---------------------------------------------------------------------------
// spmm_csr: one warp per row. Lane owns 2 output cols (float2).
// Register accumulation, bias folded in, single plain store. No fp atomics.
// ---------------------------------------------------------------------------
__global__ __launch_bounds__(256)
void spmm_csr_kernel(const float* __restrict__ support,
                     const float* __restrict__ bias,
                     float* __restrict__ out,
                     int n_nodes)
{
    int w = (blockIdx.x * 256 + threadIdx.x) >> 5;
    int lane = threadIdx.x & 31;
    if (w >= n_nodes) return;

    int start = g_row_start[w];
    int end   = start + g_deg[w];

    float ax = 0.0f, ay = 0.0f;
    int e = start;
    for (; e + 4 <= end; e += 4) {
        int   c0 = __ldg(g_ecol + e),     c1 = __ldg(g_ecol + e + 1);
        int   c2 = __ldg(g_ecol + e + 2), c3 = __ldg(g_ecol + e + 3);
        float v0 = __ldg(g_eval + e),     v1 = __ldg(g_eval + e + 1);
        float v2 = __ldg(g_eval + e + 2), v3 = __ldg(g_eval + e + 3);
        float2 s0 = *reinterpret_cast<const float2*>(support + (size_t)c0 * OUT_F + lane * 2);
        float2 s1 = *reinterpret_cast<const float2*>(support + (size_t)c1 * OUT_F + lane * 2);
        float2 s2 = *reinterpret_cast<const float2*>(support + (size_t)c2 * OUT_F + lane * 2);
        float2 s3 = *reinterpret_cast<const float2*>(support + (size_t)c3 * OUT_F + lane * 2);
        ax = fmaf(v0, s0.x, ax); ay = fmaf(v0, s0.y, ay);
        ax = fmaf(v1, s1.x, ax); ay = fmaf(v1, s1.y, ay);
        ax = fmaf(v2, s2.x, ax); ay = fmaf(v2, s2.y, ay);
        ax = fmaf(v3, s3.x, ax); ay = fmaf(v3, s3.y, ay);
    }
    for (; e < end; e++) {
        int   c = __ldg(g_ecol + e);
        float v = __ldg(g_eval + e);
        float2 s = *reinterpret_cast<const float2*>(support + (size_t)c * OUT_F + lane * 2);
        ax = fmaf(v, s.x, ax); ay = fmaf(v, s.y, ay);
    }

    float2 bv = *reinterpret_cast<const float2*>(bias + lane * 2);
    *reinterpret_cast<float2*>(out + (size_t)w * OUT_F + lane * 2) =
        make_float2(ax + bv.x, ay + bv.y);
}

// ---------------------------------------------------------------------------
// Launch.  Inputs (metadata order): x, adj_row, adj_col, adj_vals, weight, b
// ---------------------------------------------------------------------------
extern "C" void kernel_launch(void* const* d_in, const int* in_sizes, int n_in,
                              void* d_out, int out_size)
{
    const float* x        = (const float*)d_in[0];
    const int*   adj_row  = (const int*)  d_in[1];
    const int*   adj_col  = (const int*)  d_in[2];
    const float* adj_vals = (const float*)d_in[3];
    const float* weight   = (const float*)d_in[4];
    const float* b        = (const float*)d_in[5];
    float* out = (float*)d_out;

    const int n_nodes = in_sizes[0] / IN_F;
    const int n_edges = in_sizes[1];

    float* support = nullptr;
    cudaGetSymbolAddress((void**)&support, g_support);
    void* degp = nullptr;
    cudaGetSymbolAddress(&degp, g_deg);

    cudaFuncSetAttribute(gemm_mma_kernel,
                         cudaFuncAttributeMaxDynamicSharedMemorySize, 65536);

    const int eb = (n_edges + 255) / 256;
    const int nscan = (n_nodes + SCAN_CHUNK - 1) / SCAN_CHUNK;

    // CSR build front half (independent of x/W)
    cudaMemsetAsync(degp, 0, (size_t)n_nodes * sizeof(int));
    hist_kernel<<<eb, 256>>>(adj_row, n_edges);

    // W pack + GEMM
    prep_w_kernel<<<16, 256>>>(weight);
    int gemm_blocks = (n_nodes + 127) / 128;
    gemm_mma_kernel<<<gemm_blocks, 256, 65536>>>(x, support, n_nodes);

    // CSR build back half
    scan1_kernel<<<nscan, SCAN_T>>>(n_nodes);
    scan2_kernel<<<1, 32>>>(nscan);
    scan3_kernel<<<(n_nodes + 255) / 256, 256>>>(n_nodes);
    scatter_kernel<<<eb, 256>>>(adj_row, adj_col, adj_vals, n_edges);

    // SpMM over CSR, bias folded in
    int warps = n_nodes;
    int blocks = (warps * 32 + 255) / 256;
    spmm_csr_kernel<<<blocks, 256>>>(support, b, out, n_nodes);
}

// round 9
// speedup vs baseline: 1.9232x; 1.1038x over previous
#include <cuda_runtime.h>
#include <cuda_bf16.h>
#include <cstdint>

#define IN_F   256
#define OUT_F  64
#define MAX_NODES 100000
#define MAX_EDGES 1600000

// ---------------------------------------------------------------------------
// Device scratch (no allocation APIs allowed)
// ---------------------------------------------------------------------------
__device__ float g_support[(size_t)MAX_NODES * OUT_F];
__device__ unsigned long long g_bfrag[2 * 16 * 8 * 32];   // W mma fragments

// CSR build scratch
__device__ int   g_deg[MAX_NODES];        // per-row edge count (histogram)
__device__ int   g_rs[MAX_NODES];         // in-block exclusive scan
__device__ int   g_part[64];              // per-scan-block totals
__device__ int   g_row_start[MAX_NODES];  // final exclusive scan
__device__ int   g_cursor[MAX_NODES];     // scatter cursors
__device__ int   g_ecol[MAX_EDGES];       // CSR cols
__device__ float g_eval[MAX_EDGES];       // CSR vals

#define SCAN_T 512
#define SCAN_E 8
#define SCAN_CHUNK (SCAN_T * SCAN_E)      // 4096

// ---------------------------------------------------------------------------
// helpers
// ---------------------------------------------------------------------------
__device__ __forceinline__ uint32_t bfpack(float a, float b) {
    __nv_bfloat162 t = __floats2bfloat162_rn(a, b);
    return *reinterpret_cast<uint32_t*>(&t);
}
__device__ __forceinline__ void bfsplit(float v, float& hi, float& lo) {
    __nv_bfloat16 h = __float2bfloat16(v);
    hi = __bfloat162float(h);
    lo = v - hi;
}
// pack pair -> (hi_pair, lo_pair) with shift-based hi reconstruction
__device__ __forceinline__ void split_pair(float vx, float vy,
                                           uint32_t& hp, uint32_t& lp) {
    hp = bfpack(vx, vy);
    float hx = __uint_as_float(hp << 16);
    float hy = __uint_as_float(hp & 0xffff0000u);
    lp = bfpack(vx - hx, vy - hy);
}
__device__ __forceinline__ void mma_bf16(float* c, const uint32_t* a,
                                         uint32_t b0, uint32_t b1) {
    asm volatile(
        "mma.sync.aligned.m16n8k16.row.col.f32.bf16.bf16.f32 "
        "{%0,%1,%2,%3}, {%4,%5,%6,%7}, {%8,%9}, {%0,%1,%2,%3};"
        : "+f"(c[0]), "+f"(c[1]), "+f"(c[2]), "+f"(c[3])
        : "r"(a[0]), "r"(a[1]), "r"(a[2]), "r"(a[3]), "r"(b0), "r"(b1));
}

// ---------------------------------------------------------------------------
// Kernel 0: pack W into per-lane B fragments (hi and lo bf16 images).
// ---------------------------------------------------------------------------
__global__ __launch_bounds__(256)
void prep_w_kernel(const float* __restrict__ w) {
    int idx = blockIdx.x * 256 + threadIdx.x;   // 0 .. 4095
    if (idx >= 16 * 8 * 32) return;
    int lane = idx & 31;
    int nt   = (idx >> 5) & 7;
    int ks   = idx >> 8;

    int col = nt * 8 + (lane >> 2);
    int r   = ks * 16 + (lane & 3) * 2;

    float v0 = w[(size_t)(r    ) * OUT_F + col];
    float v1 = w[(size_t)(r + 1) * OUT_F + col];
    float v2 = w[(size_t)(r + 8) * OUT_F + col];
    float v3 = w[(size_t)(r + 9) * OUT_F + col];

    float h0,l0,h1,l1,h2,l2,h3,l3;
    bfsplit(v0,h0,l0); bfsplit(v1,h1,l1); bfsplit(v2,h2,l2); bfsplit(v3,h3,l3);

    unsigned long long hi = (unsigned long long)bfpack(h0,h1)
                          | ((unsigned long long)bfpack(h2,h3) << 32);
    unsigned long long lo = (unsigned long long)bfpack(l0,l1)
                          | ((unsigned long long)bfpack(l2,l3) << 32);

    g_bfrag[idx]           = hi;
    g_bfrag[16*8*32 + idx] = lo;
}

// ---------------------------------------------------------------------------
// Kernel 1: GEMM via mma.sync bf16, 3-pass split precision (proven R5/R7)
// ---------------------------------------------------------------------------
__global__ __launch_bounds__(256)
void gemm_mma_kernel(const float* __restrict__ x,
                     float* __restrict__ support,
                     int n_nodes)
{
    extern __shared__ unsigned long long sm_bfrag[];   // 64 KB

    const int tid  = threadIdx.x;
    const int wid  = tid >> 5;
    const int lane = tid & 31;

    {
        const float4* src = reinterpret_cast<const float4*>(g_bfrag);
        float4* dst = reinterpret_cast<float4*>(sm_bfrag);
#pragma unroll
        for (int i = 0; i < 16; i++)
            dst[tid + i * 256] = src[tid + i * 256];
    }
    __syncthreads();

    const int row_base = blockIdx.x * 128 + wid * 16;
    int r0 = row_base + (lane >> 2);
    int r1 = r0 + 8;
    int r0c = (r0 < n_nodes) ? r0 : (n_nodes - 1);
    int r1c = (r1 < n_nodes) ? r1 : (n_nodes - 1);
    const float* xr0 = x + (size_t)r0c * IN_F;
    const float* xr1 = x + (size_t)r1c * IN_F;
    const int cbase = (lane & 3) * 2;

    float acc[8][4];
#pragma unroll
    for (int nt = 0; nt < 8; nt++)
#pragma unroll
        for (int j = 0; j < 4; j++) acc[nt][j] = 0.0f;

#pragma unroll 4
    for (int ks = 0; ks < 16; ks++) {
        int c0 = ks * 16 + cbase;
        float2 p00 = *reinterpret_cast<const float2*>(xr0 + c0);
        float2 p10 = *reinterpret_cast<const float2*>(xr1 + c0);
        float2 p01 = *reinterpret_cast<const float2*>(xr0 + c0 + 8);
        float2 p11 = *reinterpret_cast<const float2*>(xr1 + c0 + 8);

        uint32_t ahi[4], alo[4];
        split_pair(p00.x, p00.y, ahi[0], alo[0]);
        split_pair(p10.x, p10.y, ahi[1], alo[1]);
        split_pair(p01.x, p01.y, ahi[2], alo[2]);
        split_pair(p11.x, p11.y, ahi[3], alo[3]);

        const unsigned long long* bh = sm_bfrag + (size_t)ks * (8 * 32) + lane;
        unsigned long long bf[8];
#pragma unroll
        for (int nt = 0; nt < 8; nt++) bf[nt] = bh[nt * 32];
#pragma unroll
        for (int nt = 0; nt < 8; nt++) {
            uint32_t b0 = (uint32_t)bf[nt], b1 = (uint32_t)(bf[nt] >> 32);
            mma_bf16(acc[nt], ahi, b0, b1);
            mma_bf16(acc[nt], alo, b0, b1);
        }
        const unsigned long long* bl = bh + 16 * 8 * 32;
#pragma unroll
        for (int nt = 0; nt < 8; nt++) bf[nt] = bl[nt * 32];
#pragma unroll
        for (int nt = 0; nt < 8; nt++) {
            uint32_t b0 = (uint32_t)bf[nt], b1 = (uint32_t)(bf[nt] >> 32);
            mma_bf16(acc[nt], ahi, b0, b1);
        }
    }

    if (r0 < n_nodes) {
        float* d = support + (size_t)r0 * OUT_F + cbase;
#pragma unroll
        for (int nt = 0; nt < 8; nt++)
            *reinterpret_cast<float2*>(d + nt * 8) = make_float2(acc[nt][0], acc[nt][1]);
    }
    if (r1 < n_nodes) {
        float* d = support + (size_t)r1 * OUT_F + cbase;
#pragma unroll
        for (int nt = 0; nt < 8; nt++)
            *reinterpret_cast<float2*>(d + nt * 8) = make_float2(acc[nt][2], acc[nt][3]);
    }
}

// ---------------------------------------------------------------------------
// CSR build
// ---------------------------------------------------------------------------
__global__ __launch_bounds__(256)
void hist_kernel(const int* __restrict__ adj_row, int n_edges) {
    int e = blockIdx.x * 256 + threadIdx.x;
    if (e < n_edges) atomicAdd(&g_deg[adj_row[e]], 1);
}

// scan1: per-block exclusive scan of deg into g_rs, block totals into g_part
__global__ __launch_bounds__(SCAN_T)
void scan1_kernel(int n) {
    __shared__ int s[SCAN_T];
    const int tid = threadIdx.x;
    const int base = blockIdx.x * SCAN_CHUNK + tid * SCAN_E;

    int c[SCAN_E];
    int tsum = 0;
#pragma unroll
    for (int j = 0; j < SCAN_E; j++) {
        int idx = base + j;
        c[j] = (idx < n) ? g_deg[idx] : 0;
        tsum += c[j];
    }
    s[tid] = tsum;
    __syncthreads();
    for (int off = 1; off < SCAN_T; off <<= 1) {
        int v = (tid >= off) ? s[tid - off] : 0;
        __syncthreads();
        s[tid] += v;
        __syncthreads();
    }
    int excl = s[tid] - tsum;
    if (tid == SCAN_T - 1) g_part[blockIdx.x] = s[tid];  // block total
#pragma unroll
    for (int j = 0; j < SCAN_E; j++) {
        int idx = base + j;
        if (idx < n) g_rs[idx] = excl;
        excl += c[j];
    }
}

// scan3: warp-scan the <=32 block totals inline, add offsets,
// init row_start + cursor.  (scan2 eliminated)
__global__ __launch_bounds__(256)
void scan3_kernel(int n, int nblocks) {
    __shared__ int soff[32];
    int t = threadIdx.x;
    if (t < 32) {
        int orig = (t < nblocks) ? g_part[t] : 0;
        int v = orig;
#pragma unroll
        for (int o = 1; o < 32; o <<= 1) {
            int u = __shfl_up_sync(0xffffffff, v, o);
            if (t >= o) v += u;
        }
        soff[t] = v - orig;   // exclusive prefix
    }
    __syncthreads();
    int idx = blockIdx.x * 256 + t;
    if (idx < n) {
        int v = g_rs[idx] + soff[idx / SCAN_CHUNK];
        g_row_start[idx] = v;
        g_cursor[idx] = v;
    }
}

__global__ __launch_bounds__(256)
void scatter_kernel(const int* __restrict__ adj_row,
                    const int* __restrict__ adj_col,
                    const float* __restrict__ adj_vals,
                    int n_edges) {
    int e = blockIdx.x * 256 + threadIdx.x;
    if (e < n_edges) {
        int r = adj_row[e];
        int pos = atomicAdd(&g_cursor[r], 1);
        g_ecol[pos] = adj_col[e];
        g_eval[pos] = adj_vals[e];
    }
}

// ---------------------------------------------------------------------------
// spmm_csr: one warp per row. Lane owns 2 output cols (float2).
// Register accumulation, bias folded in, single plain store. No fp atomics.
// ---------------------------------------------------------------------------
__global__ __launch_bounds__(256)
void spmm_csr_kernel(const float* __restrict__ support,
                     const float* __restrict__ bias,
                     float* __restrict__ out,
                     int n_nodes)
{
    int w = (blockIdx.x * 256 + threadIdx.x) >> 5;
    int lane = threadIdx.x & 31;
    if (w >= n_nodes) return;

    int start = __ldg(g_row_start + w);
    int end   = start + __ldg(g_deg + w);

    float ax = 0.0f, ay = 0.0f;
    int e = start;
#pragma unroll 1
    for (; e + 8 <= end; e += 8) {
        int c[8]; float v[8]; float2 s[8];
#pragma unroll
        for (int j = 0; j < 8; j++) {
            c[j] = __ldg(g_ecol + e + j);
            v[j] = __ldg(g_eval + e + j);
        }
#pragma unroll
        for (int j = 0; j < 8; j++)
            s[j] = *reinterpret_cast<const float2*>(
                support + (size_t)c[j] * OUT_F + lane * 2);
#pragma unroll
        for (int j = 0; j < 8; j++) {
            ax = fmaf(v[j], s[j].x, ax);
            ay = fmaf(v[j], s[j].y, ay);
        }
    }
    for (; e < end; e++) {
        int   c = __ldg(g_ecol + e);
        float v = __ldg(g_eval + e);
        float2 s = *reinterpret_cast<const float2*>(support + (size_t)c * OUT_F + lane * 2);
        ax = fmaf(v, s.x, ax); ay = fmaf(v, s.y, ay);
    }

    float2 bv = *reinterpret_cast<const float2*>(bias + lane * 2);
    *reinterpret_cast<float2*>(out + (size_t)w * OUT_F + lane * 2) =
        make_float2(ax + bv.x, ay + bv.y);
}

// ---------------------------------------------------------------------------
// Launch.  Inputs (metadata order): x, adj_row, adj_col, adj_vals, weight, b
// Fork/join: CSR build (side stream) overlaps prep_w + GEMM (stream 0).
// Stream/events created ONCE (host handles, not device memory).
// ---------------------------------------------------------------------------
extern "C" void kernel_launch(void* const* d_in, const int* in_sizes, int n_in,
                              void* d_out, int out_size)
{
    const float* x        = (const float*)d_in[0];
    const int*   adj_row  = (const int*)  d_in[1];
    const int*   adj_col  = (const int*)  d_in[2];
    const float* adj_vals = (const float*)d_in[3];
    const float* weight   = (const float*)d_in[4];
    const float* b        = (const float*)d_in[5];
    float* out = (float*)d_out;

    const int n_nodes = in_sizes[0] / IN_F;
    const int n_edges = in_sizes[1];

    float* support = nullptr;
    cudaGetSymbolAddress((void**)&support, g_support);
    void* degp = nullptr;
    cudaGetSymbolAddress(&degp, g_deg);

    cudaFuncSetAttribute(gemm_mma_kernel,
                         cudaFuncAttributeMaxDynamicSharedMemorySize, 65536);

    const int eb = (n_edges + 255) / 256;
    const int nscan = (n_nodes + SCAN_CHUNK - 1) / SCAN_CHUNK;

    // One-time host handle creation (no device allocation; same graph topology
    // captured on every call).
    static cudaStream_t s2 = nullptr;
    static cudaEvent_t evFork = nullptr, evJoin = nullptr;
    if (!s2) {
        cudaStreamCreateWithFlags(&s2, cudaStreamNonBlocking);
        cudaEventCreateWithFlags(&evFork, cudaEventDisableTiming);
        cudaEventCreateWithFlags(&evJoin, cudaEventDisableTiming);
    }

    // ---- fork: CSR build on s2
    cudaEventRecord(evFork, 0);
    cudaStreamWaitEvent(s2, evFork, 0);

    cudaMemsetAsync(degp, 0, (size_t)n_nodes * sizeof(int), s2);
    hist_kernel<<<eb, 256, 0, s2>>>(adj_row, n_edges);
    scan1_kernel<<<nscan, SCAN_T, 0, s2>>>(n_nodes);
    scan3_kernel<<<(n_nodes + 255) / 256, 256, 0, s2>>>(n_nodes, nscan);
    scatter_kernel<<<eb, 256, 0, s2>>>(adj_row, adj_col, adj_vals, n_edges);

    // ---- stream 0: W pack + GEMM (independent of CSR build)
    prep_w_kernel<<<16, 256>>>(weight);
    int gemm_blocks = (n_nodes + 127) / 128;
    gemm_mma_kernel<<<gemm_blocks, 256, 65536>>>(x, support, n_nodes);

    // ---- join
    cudaEventRecord(evJoin, s2);
    cudaStreamWaitEvent(0, evJoin, 0);

    // ---- SpMM over CSR, bias folded in
    int blocks = (n_nodes * 32 + 255) / 256;
    spmm_csr_kernel<<<blocks, 256>>>(support, b, out, n_nodes);
}

// round 10
// speedup vs baseline: 1.9817x; 1.0304x over previous
#include <cuda_runtime.h>
#include <cuda_bf16.h>
#include <cstdint>

#define IN_F   256
#define OUT_F  64
#define MAX_NODES 100000
#define MAX_EDGES 1600000

// ---------------------------------------------------------------------------
// Device scratch (no allocation APIs allowed)
// ---------------------------------------------------------------------------
__device__ float g_support[(size_t)MAX_NODES * OUT_F];
__device__ unsigned long long g_bfrag[2 * 16 * 8 * 32];   // W mma fragments

// CSR build scratch
__device__ int   g_deg[MAX_NODES];        // per-row edge count (histogram)
__device__ int   g_rs[MAX_NODES];         // in-block exclusive scan
__device__ int   g_part[64];              // per-scan-block totals
__device__ int   g_row_start[MAX_NODES];  // final exclusive scan
__device__ int   g_slot[MAX_EDGES];       // within-row slot per edge (from hist)
__device__ int2  g_epack[MAX_EDGES];      // CSR packed {col, val_bits}

#define SCAN_T 512
#define SCAN_E 8
#define SCAN_CHUNK (SCAN_T * SCAN_E)      // 4096

// ---------------------------------------------------------------------------
// helpers
// ---------------------------------------------------------------------------
__device__ __forceinline__ uint32_t bfpack(float a, float b) {
    __nv_bfloat162 t = __floats2bfloat162_rn(a, b);
    return *reinterpret_cast<uint32_t*>(&t);
}
__device__ __forceinline__ void bfsplit(float v, float& hi, float& lo) {
    __nv_bfloat16 h = __float2bfloat16(v);
    hi = __bfloat162float(h);
    lo = v - hi;
}
// pack pair -> (hi_pair, lo_pair) with shift-based hi reconstruction
__device__ __forceinline__ void split_pair(float vx, float vy,
                                           uint32_t& hp, uint32_t& lp) {
    hp = bfpack(vx, vy);
    float hx = __uint_as_float(hp << 16);
    float hy = __uint_as_float(hp & 0xffff0000u);
    lp = bfpack(vx - hx, vy - hy);
}
__device__ __forceinline__ void mma_bf16(float* c, const uint32_t* a,
                                         uint32_t b0, uint32_t b1) {
    asm volatile(
        "mma.sync.aligned.m16n8k16.row.col.f32.bf16.bf16.f32 "
        "{%0,%1,%2,%3}, {%4,%5,%6,%7}, {%8,%9}, {%0,%1,%2,%3};"
        : "+f"(c[0]), "+f"(c[1]), "+f"(c[2]), "+f"(c[3])
        : "r"(a[0]), "r"(a[1]), "r"(a[2]), "r"(a[3]), "r"(b0), "r"(b1));
}

// ---------------------------------------------------------------------------
// Kernel 0: pack W into per-lane B fragments (hi and lo bf16 images).
// ---------------------------------------------------------------------------
__global__ __launch_bounds__(256)
void prep_w_kernel(const float* __restrict__ w) {
    int idx = blockIdx.x * 256 + threadIdx.x;   // 0 .. 4095
    if (idx >= 16 * 8 * 32) return;
    int lane = idx & 31;
    int nt   = (idx >> 5) & 7;
    int ks   = idx >> 8;

    int col = nt * 8 + (lane >> 2);
    int r   = ks * 16 + (lane & 3) * 2;

    float v0 = w[(size_t)(r    ) * OUT_F + col];
    float v1 = w[(size_t)(r + 1) * OUT_F + col];
    float v2 = w[(size_t)(r + 8) * OUT_F + col];
    float v3 = w[(size_t)(r + 9) * OUT_F + col];

    float h0,l0,h1,l1,h2,l2,h3,l3;
    bfsplit(v0,h0,l0); bfsplit(v1,h1,l1); bfsplit(v2,h2,l2); bfsplit(v3,h3,l3);

    unsigned long long hi = (unsigned long long)bfpack(h0,h1)
                          | ((unsigned long long)bfpack(h2,h3) << 32);
    unsigned long long lo = (unsigned long long)bfpack(l0,l1)
                          | ((unsigned long long)bfpack(l2,l3) << 32);

    g_bfrag[idx]           = hi;
    g_bfrag[16*8*32 + idx] = lo;
}

// ---------------------------------------------------------------------------
// Kernel 1: GEMM via mma.sync bf16, 3-pass split precision (proven R5/R7)
// ---------------------------------------------------------------------------
__global__ __launch_bounds__(256)
void gemm_mma_kernel(const float* __restrict__ x,
                     float* __restrict__ support,
                     int n_nodes)
{
    extern __shared__ unsigned long long sm_bfrag[];   // 64 KB

    const int tid  = threadIdx.x;
    const int wid  = tid >> 5;
    const int lane = tid & 31;

    {
        const float4* src = reinterpret_cast<const float4*>(g_bfrag);
        float4* dst = reinterpret_cast<float4*>(sm_bfrag);
#pragma unroll
        for (int i = 0; i < 16; i++)
            dst[tid + i * 256] = src[tid + i * 256];
    }
    __syncthreads();

    const int row_base = blockIdx.x * 128 + wid * 16;
    int r0 = row_base + (lane >> 2);
    int r1 = r0 + 8;
    int r0c = (r0 < n_nodes) ? r0 : (n_nodes - 1);
    int r1c = (r1 < n_nodes) ? r1 : (n_nodes - 1);
    const float* xr0 = x + (size_t)r0c * IN_F;
    const float* xr1 = x + (size_t)r1c * IN_F;
    const int cbase = (lane & 3) * 2;

    float acc[8][4];
#pragma unroll
    for (int nt = 0; nt < 8; nt++)
#pragma unroll
        for (int j = 0; j < 4; j++) acc[nt][j] = 0.0f;

#pragma unroll 4
    for (int ks = 0; ks < 16; ks++) {
        int c0 = ks * 16 + cbase;
        float2 p00 = *reinterpret_cast<const float2*>(xr0 + c0);
        float2 p10 = *reinterpret_cast<const float2*>(xr1 + c0);
        float2 p01 = *reinterpret_cast<const float2*>(xr0 + c0 + 8);
        float2 p11 = *reinterpret_cast<const float2*>(xr1 + c0 + 8);

        uint32_t ahi[4], alo[4];
        split_pair(p00.x, p00.y, ahi[0], alo[0]);
        split_pair(p10.x, p10.y, ahi[1], alo[1]);
        split_pair(p01.x, p01.y, ahi[2], alo[2]);
        split_pair(p11.x, p11.y, ahi[3], alo[3]);

        const unsigned long long* bh = sm_bfrag + (size_t)ks * (8 * 32) + lane;
        unsigned long long bf[8];
#pragma unroll
        for (int nt = 0; nt < 8; nt++) bf[nt] = bh[nt * 32];
#pragma unroll
        for (int nt = 0; nt < 8; nt++) {
            uint32_t b0 = (uint32_t)bf[nt], b1 = (uint32_t)(bf[nt] >> 32);
            mma_bf16(acc[nt], ahi, b0, b1);
            mma_bf16(acc[nt], alo, b0, b1);
        }
        const unsigned long long* bl = bh + 16 * 8 * 32;
#pragma unroll
        for (int nt = 0; nt < 8; nt++) bf[nt] = bl[nt * 32];
#pragma unroll
        for (int nt = 0; nt < 8; nt++) {
            uint32_t b0 = (uint32_t)bf[nt], b1 = (uint32_t)(bf[nt] >> 32);
            mma_bf16(acc[nt], ahi, b0, b1);
        }
    }

    if (r0 < n_nodes) {
        float* d = support + (size_t)r0 * OUT_F + cbase;
#pragma unroll
        for (int nt = 0; nt < 8; nt++)
            *reinterpret_cast<float2*>(d + nt * 8) = make_float2(acc[nt][0], acc[nt][1]);
    }
    if (r1 < n_nodes) {
        float* d = support + (size_t)r1 * OUT_F + cbase;
#pragma unroll
        for (int nt = 0; nt < 8; nt++)
            *reinterpret_cast<float2*>(d + nt * 8) = make_float2(acc[nt][2], acc[nt][3]);
    }
}

// ---------------------------------------------------------------------------
// CSR build
// ---------------------------------------------------------------------------
// hist: count per-row degree AND record each edge's within-row slot.
__global__ __launch_bounds__(256)
void hist_kernel(const int* __restrict__ adj_row, int n_edges) {
    int e = blockIdx.x * 256 + threadIdx.x;
    if (e < n_edges)
        g_slot[e] = atomicAdd(&g_deg[adj_row[e]], 1);
}

// scan1: per-block exclusive scan of deg into g_rs, block totals into g_part
__global__ __launch_bounds__(SCAN_T)
void scan1_kernel(int n) {
    __shared__ int s[SCAN_T];
    const int tid = threadIdx.x;
    const int base = blockIdx.x * SCAN_CHUNK + tid * SCAN_E;

    int c[SCAN_E];
    int tsum = 0;
#pragma unroll
    for (int j = 0; j < SCAN_E; j++) {
        int idx = base + j;
        c[j] = (idx < n) ? g_deg[idx] : 0;
        tsum += c[j];
    }
    s[tid] = tsum;
    __syncthreads();
    for (int off = 1; off < SCAN_T; off <<= 1) {
        int v = (tid >= off) ? s[tid - off] : 0;
        __syncthreads();
        s[tid] += v;
        __syncthreads();
    }
    int excl = s[tid] - tsum;
    if (tid == SCAN_T - 1) g_part[blockIdx.x] = s[tid];  // block total
#pragma unroll
    for (int j = 0; j < SCAN_E; j++) {
        int idx = base + j;
        if (idx < n) g_rs[idx] = excl;
        excl += c[j];
    }
}

// scan3: warp-scan the <=32 block totals inline, add offsets, write row_start.
__global__ __launch_bounds__(256)
void scan3_kernel(int n, int nblocks) {
    __shared__ int soff[32];
    int t = threadIdx.x;
    if (t < 32) {
        int orig = (t < nblocks) ? g_part[t] : 0;
        int v = orig;
#pragma unroll
        for (int o = 1; o < 32; o <<= 1) {
            int u = __shfl_up_sync(0xffffffff, v, o);
            if (t >= o) v += u;
        }
        soff[t] = v - orig;   // exclusive prefix
    }
    __syncthreads();
    int idx = blockIdx.x * 256 + t;
    if (idx < n)
        g_row_start[idx] = g_rs[idx] + soff[idx / SCAN_CHUNK];
}

// scatter: NO atomics — pos = row_start[row] + slot. One 8B packed store.
__global__ __launch_bounds__(256)
void scatter_kernel(const int* __restrict__ adj_row,
                    const int* __restrict__ adj_col,
                    const float* __restrict__ adj_vals,
                    int n_edges) {
    int e = blockIdx.x * 256 + threadIdx.x;
    if (e < n_edges) {
        int r = adj_row[e];
        int pos = __ldg(g_row_start + r) + g_slot[e];
        g_epack[pos] = make_int2(adj_col[e], __float_as_int(adj_vals[e]));
    }
}

// ---------------------------------------------------------------------------
// spmm_csr: one warp per row. Lane owns 2 output cols (float2).
// Register accumulation, bias folded in, single plain store. No fp atomics.
// ---------------------------------------------------------------------------
__global__ __launch_bounds__(256)
void spmm_csr_kernel(const float* __restrict__ support,
                     const float* __restrict__ bias,
                     float* __restrict__ out,
                     int n_nodes)
{
    int w = (blockIdx.x * 256 + threadIdx.x) >> 5;
    int lane = threadIdx.x & 31;
    if (w >= n_nodes) return;

    int start = __ldg(g_row_start + w);
    int end   = start + __ldg(g_deg + w);

    float ax = 0.0f, ay = 0.0f;
    int e = start;
#pragma unroll 1
    for (; e + 8 <= end; e += 8) {
        int2 p[8]; float2 s[8];
#pragma unroll
        for (int j = 0; j < 8; j++) p[j] = __ldg(g_epack + e + j);
#pragma unroll
        for (int j = 0; j < 8; j++)
            s[j] = *reinterpret_cast<const float2*>(
                support + (size_t)p[j].x * OUT_F + lane * 2);
#pragma unroll
        for (int j = 0; j < 8; j++) {
            float v = __int_as_float(p[j].y);
            ax = fmaf(v, s[j].x, ax);
            ay = fmaf(v, s[j].y, ay);
        }
    }
    for (; e < end; e++) {
        int2 p = __ldg(g_epack + e);
        float v = __int_as_float(p.y);
        float2 s = *reinterpret_cast<const float2*>(
            support + (size_t)p.x * OUT_F + lane * 2);
        ax = fmaf(v, s.x, ax); ay = fmaf(v, s.y, ay);
    }

    float2 bv = *reinterpret_cast<const float2*>(bias + lane * 2);
    *reinterpret_cast<float2*>(out + (size_t)w * OUT_F + lane * 2) =
        make_float2(ax + bv.x, ay + bv.y);
}

// ---------------------------------------------------------------------------
// Launch.  Inputs (metadata order): x, adj_row, adj_col, adj_vals, weight, b
// Fork/join: CSR build (side stream) overlaps prep_w + GEMM (stream 0).
// ---------------------------------------------------------------------------
extern "C" void kernel_launch(void* const* d_in, const int* in_sizes, int n_in,
                              void* d_out, int out_size)
{
    const float* x        = (const float*)d_in[0];
    const int*   adj_row  = (const int*)  d_in[1];
    const int*   adj_col  = (const int*)  d_in[2];
    const float* adj_vals = (const float*)d_in[3];
    const float* weight   = (const float*)d_in[4];
    const float* b        = (const float*)d_in[5];
    float* out = (float*)d_out;

    const int n_nodes = in_sizes[0] / IN_F;
    const int n_edges = in_sizes[1];

    float* support = nullptr;
    cudaGetSymbolAddress((void**)&support, g_support);
    void* degp = nullptr;
    cudaGetSymbolAddress(&degp, g_deg);

    cudaFuncSetAttribute(gemm_mma_kernel,
                         cudaFuncAttributeMaxDynamicSharedMemorySize, 65536);

    const int eb = (n_edges + 255) / 256;
    const int nscan = (n_nodes + SCAN_CHUNK - 1) / SCAN_CHUNK;

    // One-time host handle creation (no device allocation; same graph topology
    // captured on every call).
    static cudaStream_t s2 = nullptr;
    static cudaEvent_t evFork = nullptr, evJoin = nullptr;
    if (!s2) {
        cudaStreamCreateWithFlags(&s2, cudaStreamNonBlocking);
        cudaEventCreateWithFlags(&evFork, cudaEventDisableTiming);
        cudaEventCreateWithFlags(&evJoin, cudaEventDisableTiming);
    }

    // ---- fork: CSR build on s2
    cudaEventRecord(evFork, 0);
    cudaStreamWaitEvent(s2, evFork, 0);

    cudaMemsetAsync(degp, 0, (size_t)n_nodes * sizeof(int), s2);
    hist_kernel<<<eb, 256, 0, s2>>>(adj_row, n_edges);
    scan1_kernel<<<nscan, SCAN_T, 0, s2>>>(n_nodes);
    scan3_kernel<<<(n_nodes + 255) / 256, 256, 0, s2>>>(n_nodes, nscan);
    scatter_kernel<<<eb, 256, 0, s2>>>(adj_row, adj_col, adj_vals, n_edges);

    // ---- stream 0: W pack + GEMM (independent of CSR build)
    prep_w_kernel<<<16, 256>>>(weight);
    int gemm_blocks = (n_nodes + 127) / 128;
    gemm_mma_kernel<<<gemm_blocks, 256, 65536>>>(x, support, n_nodes);

    // ---- join
    cudaEventRecord(evJoin, s2);
    cudaStreamWaitEvent(0, evJoin, 0);

    // ---- SpMM over CSR, bias folded in
    int blocks = (n_nodes * 32 + 255) / 256;
    spmm_csr_kernel<<<blocks, 256>>>(support, b, out, n_nodes);
}